// round 13
// baseline (speedup 1.0000x reference)
#include <cuda_runtime.h>
#include <cuda_bf16.h>
#include <math.h>

#define N_NODES 100000
#define N_EDGES 1600000
#define E_TOT   (N_EDGES + N_NODES)
#define NEG_SLOPE 0.2f

// ---------------- scratch (static device globals) ---------------------------
__device__ __align__(16) float g_xw1[N_NODES * 128];
__device__ __align__(16) float g_al1[N_NODES * 4];
__device__ __align__(16) float g_ar1[N_NODES * 4];
__device__ __align__(16) float g_xw2[N_NODES * 16];
__device__ __align__(16) float g_al2[N_NODES];
__device__ __align__(16) float g_ar2[N_NODES];
__device__ int g_deg[N_NODES];     // in-degree (incl. self loop)
__device__ int g_row[N_NODES];     // CSR row start
__device__ int g_fill[N_NODES];    // scatter cursor
__device__ int g_csr_src[E_TOT];   // src node id per CSR slot
__device__ int g_cursor;           // global allocation cursor for scan

// ---------------- helpers ---------------------------------------------------
__device__ __forceinline__ float lrelu(float v) {
    return v > 0.f ? v : NEG_SLOPE * v;
}
// packed f32x2 ops (B300: FFMA2 = full-rate fp32; scalar FFMA is half-rate)
__device__ __forceinline__ unsigned long long pack2(float lo, float hi) {
    unsigned long long r;
    asm("mov.b64 %0, {%1, %2};" : "=l"(r) : "f"(lo), "f"(hi));
    return r;
}
__device__ __forceinline__ unsigned long long fma2(unsigned long long a,
                                                   unsigned long long b,
                                                   unsigned long long c) {
    unsigned long long d;
    asm("fma.rn.f32x2 %0, %1, %2, %3;" : "=l"(d) : "l"(a), "l"(b), "l"(c));
    return d;
}

// ---------------- CSR build --------------------------------------------------
__global__ void hist_kernel(const int* __restrict__ ei) {
    for (int i = blockIdx.x * blockDim.x + threadIdx.x; i < E_TOT; i += gridDim.x * blockDim.x) {
        int d = (i < N_EDGES) ? ei[N_EDGES + i] : (i - N_EDGES);
        atomicAdd(&g_deg[d], 1);
    }
}

#define SCAN_B 256
__global__ void scan_kernel() {
    __shared__ int sdata[SCAN_B];
    __shared__ int base;
    int t = threadIdx.x;
    int d = blockIdx.x * SCAN_B + t;
    int deg = (d < N_NODES) ? g_deg[d] : 0;
    sdata[t] = deg;
    __syncthreads();
    #pragma unroll
    for (int off = 1; off < SCAN_B; off <<= 1) {
        int v = 0;
        if (t >= off) v = sdata[t - off];
        __syncthreads();
        if (t >= off) sdata[t] += v;
        __syncthreads();
    }
    int incl = sdata[t];
    int excl = incl - deg;
    if (t == SCAN_B - 1) base = atomicAdd(&g_cursor, incl);
    __syncthreads();
    if (d < N_NODES) {
        int r = base + excl;
        g_row[d]  = r;
        g_fill[d] = r;
    }
}

__global__ void scatter_kernel(const int* __restrict__ ei) {
    for (int i = blockIdx.x * blockDim.x + threadIdx.x; i < E_TOT; i += gridDim.x * blockDim.x) {
        int s, d;
        if (i < N_EDGES) { s = ei[i]; d = ei[N_EDGES + i]; }
        else             { s = d = i - N_EDGES; }
        int pos = atomicAdd(&g_fill[d], 1);
        g_csr_src[pos] = s;
    }
}

// ---------------- layer 1 GEMM: x @ W1 (packed f32x2 SGEMM) -----------------
// 128x128 output tile per block, 256 threads (16x16), TM=8 x TN=8 per thread,
// BK=16. Accumulators held as 32 packed f32x2; inner product via fma.rn.f32x2.
// Epilogue computes per-head attention dots in-register (half-warp owns a row).
#define BK1 16
#define XS_PITCH 132                 // pad to kill staging STS conflicts
__global__ void __launch_bounds__(256)
gemm1_kernel(const float* __restrict__ x,
             const float* __restrict__ W1,
             const float* __restrict__ asrc,
             const float* __restrict__ adst) {
    __shared__ __align__(16) float xs[BK1 * XS_PITCH];  // xs[k][n] transposed
    __shared__ __align__(16) float ws[BK1 * 128];       // ws[k][c]
    int t  = threadIdx.x;
    int tx = t & 15;                 // col group
    int ty = t >> 4;                 // row group
    int nbase = blockIdx.x * 128;

    unsigned long long acc[8][4];
    #pragma unroll
    for (int r = 0; r < 8; r++)
        #pragma unroll
        for (int p = 0; p < 4; p++) acc[r][p] = 0ull;

    const float4* W4 = (const float4*)W1;
    float4* ws4s = (float4*)ws;

    for (int k0 = 0; k0 < 128; k0 += BK1) {
        // stage W1 rows [k0, k0+16): 512 float4, coalesced
        #pragma unroll
        for (int i = 0; i < 2; i++)
            ws4s[t + i * 256] = W4[k0 * 32 + t + i * 256];
        // stage x tile transposed: node n (128), k chunk j (4 float4s)
        #pragma unroll
        for (int i = 0; i < 2; i++) {
            int idx = t + i * 256;
            int n = idx >> 2, j = idx & 3;
            int node = nbase + n;
            float4 v = make_float4(0.f, 0.f, 0.f, 0.f);
            if (node < N_NODES)
                v = *(const float4*)&x[(size_t)node * 128 + k0 + j * 4];
            xs[(j * 4 + 0) * XS_PITCH + n] = v.x;
            xs[(j * 4 + 1) * XS_PITCH + n] = v.y;
            xs[(j * 4 + 2) * XS_PITCH + n] = v.z;
            xs[(j * 4 + 3) * XS_PITCH + n] = v.w;
        }
        __syncthreads();

        #pragma unroll
        for (int k = 0; k < BK1; k++) {
            float4 xa = *(const float4*)&xs[k * XS_PITCH + ty * 4];
            float4 xb = *(const float4*)&xs[k * XS_PITCH + ty * 4 + 64];
            float4 wa = *(const float4*)&ws[k * 128 + tx * 4];
            float4 wb = *(const float4*)&ws[k * 128 + tx * 4 + 64];
            unsigned long long wp0 = pack2(wa.x, wa.y);
            unsigned long long wp1 = pack2(wa.z, wa.w);
            unsigned long long wp2 = pack2(wb.x, wb.y);
            unsigned long long wp3 = pack2(wb.z, wb.w);
            float xr[8] = {xa.x, xa.y, xa.z, xa.w, xb.x, xb.y, xb.z, xb.w};
            #pragma unroll
            for (int r = 0; r < 8; r++) {
                unsigned long long xx = pack2(xr[r], xr[r]);
                acc[r][0] = fma2(xx, wp0, acc[r][0]);
                acc[r][1] = fma2(xx, wp1, acc[r][1]);
                acc[r][2] = fma2(xx, wp2, acc[r][2]);
                acc[r][3] = fma2(xx, wp3, acc[r][3]);
            }
        }
        __syncthreads();
    }

    // epilogue: write rows + in-register attention dots.
    // thread covers cols [tx*4, tx*4+4) (head_lo = tx>>3) and
    // [64+tx*4, 64+tx*4+4) (head_hi = 2+(tx>>3)). 8-lane xor-reduce per head.
    float4 as_lo = ((const float4*)asrc)[tx];
    float4 as_hi = ((const float4*)asrc)[16 + tx];
    float4 ad_lo = ((const float4*)adst)[tx];
    float4 ad_hi = ((const float4*)adst)[16 + tx];
    int head_lo = tx >> 3;
    #pragma unroll
    for (int r = 0; r < 8; r++) {
        int rg = (r < 4) ? (ty * 4 + r) : (64 + ty * 4 + (r - 4));
        int node = nbase + rg;
        float2 f0 = *(float2*)&acc[r][0];
        float2 f1 = *(float2*)&acc[r][1];
        float2 f2 = *(float2*)&acc[r][2];
        float2 f3 = *(float2*)&acc[r][3];
        if (node < N_NODES) {
            *(float4*)&g_xw1[(size_t)node * 128 + tx * 4] =
                make_float4(f0.x, f0.y, f1.x, f1.y);
            *(float4*)&g_xw1[(size_t)node * 128 + 64 + tx * 4] =
                make_float4(f2.x, f2.y, f3.x, f3.y);
        }
        float al_lo = f0.x * as_lo.x + f0.y * as_lo.y + f1.x * as_lo.z + f1.y * as_lo.w;
        float al_hi = f2.x * as_hi.x + f2.y * as_hi.y + f3.x * as_hi.z + f3.y * as_hi.w;
        float ar_lo = f0.x * ad_lo.x + f0.y * ad_lo.y + f1.x * ad_lo.z + f1.y * ad_lo.w;
        float ar_hi = f2.x * ad_hi.x + f2.y * ad_hi.y + f3.x * ad_hi.z + f3.y * ad_hi.w;
        #pragma unroll
        for (int o = 4; o > 0; o >>= 1) {     // reduce within 8-lane head group
            al_lo += __shfl_xor_sync(0xffffffffu, al_lo, o);
            al_hi += __shfl_xor_sync(0xffffffffu, al_hi, o);
            ar_lo += __shfl_xor_sync(0xffffffffu, ar_lo, o);
            ar_hi += __shfl_xor_sync(0xffffffffu, ar_hi, o);
        }
        if ((tx & 7) == 0 && node < N_NODES) {
            g_al1[node * 4 + head_lo]     = al_lo;
            g_al1[node * 4 + 2 + head_lo] = al_hi;
            g_ar1[node * 4 + head_lo]     = ar_lo;
            g_ar1[node * 4 + 2 + head_lo] = ar_hi;
        }
    }
}

// ---------------- fused layer-1 aggregation + layer-2 GEMM ------------------
// One warp per dst node; zero atomics. Pass-2 gather is software-pipelined
// (next index/al/row loads issued before current row is consumed).
#define F1_WARPS 8
__global__ void fused1_kernel(const float* __restrict__ b1,
                              const float* __restrict__ W2,
                              const float* __restrict__ asrc2,
                              const float* __restrict__ adst2) {
    __shared__ __align__(16) float W2t[16 * 128];   // transposed: [c][k]
    int t = threadIdx.x;
    #pragma unroll
    for (int i = t; i < 16 * 128; i += F1_WARPS * 32) {
        int c = i >> 7, k = i & 127;
        W2t[i] = W2[k * 16 + c];
    }
    __syncthreads();

    int warp = t >> 5, lane = t & 31;
    int d = blockIdx.x * F1_WARPS + warp;
    if (d >= N_NODES) return;

    int row = g_row[d];
    int deg = g_deg[d];
    float4 ar4 = *(const float4*)&g_ar1[d * 4];

    // pass 1: per-head softmax denominators (no max; mathematically exact)
    float den0 = 0.f, den1 = 0.f, den2 = 0.f, den3 = 0.f;
    for (int i = lane; i < deg; i += 32) {
        int s = g_csr_src[row + i];
        float4 al = *(const float4*)&g_al1[s * 4];
        den0 += __expf(lrelu(al.x + ar4.x));
        den1 += __expf(lrelu(al.y + ar4.y));
        den2 += __expf(lrelu(al.z + ar4.z));
        den3 += __expf(lrelu(al.w + ar4.w));
    }
    #pragma unroll
    for (int o = 16; o > 0; o >>= 1) {
        den0 += __shfl_xor_sync(0xffffffffu, den0, o);
        den1 += __shfl_xor_sync(0xffffffffu, den1, o);
        den2 += __shfl_xor_sync(0xffffffffu, den2, o);
        den3 += __shfl_xor_sync(0xffffffffu, den3, o);
    }

    int head = lane >> 3;
    float ar_h  = (head < 2) ? (head == 0 ? ar4.x : ar4.y)
                             : (head == 2 ? ar4.z : ar4.w);
    float inv_h = (head < 2) ? (head == 0 ? den0 : den1)
                             : (head == 2 ? den2 : den3);
    inv_h = 1.f / inv_h;

    // pass 2: software-pipelined warp-collective weighted gather
    float4 acc = make_float4(0.f, 0.f, 0.f, 0.f);
    int   s_cur = g_csr_src[row];             // deg >= 1 always (self loop)
    float a_cur = g_al1[s_cur * 4 + head];
    float4 v_cur = *(const float4*)&g_xw1[(size_t)s_cur * 128 + lane * 4];
    for (int i = 0; i < deg; i++) {
        int   s_nxt = s_cur;
        float a_nxt = a_cur;
        float4 v_nxt = v_cur;
        if (i + 1 < deg) {                    // prefetch iteration i+1
            s_nxt = g_csr_src[row + i + 1];
            a_nxt = g_al1[s_nxt * 4 + head];
            v_nxt = *(const float4*)&g_xw1[(size_t)s_nxt * 128 + lane * 4];
        }
        float alpha = __expf(lrelu(a_cur + ar_h)) * inv_h;
        acc.x = fmaf(v_cur.x, alpha, acc.x);
        acc.y = fmaf(v_cur.y, alpha, acc.y);
        acc.z = fmaf(v_cur.z, alpha, acc.z);
        acc.w = fmaf(v_cur.w, alpha, acc.w);
        s_cur = s_nxt; a_cur = a_nxt; v_cur = v_nxt;
    }

    // epilogue: bias + ReLU -> h row (registers)
    float4 bb = *(const float4*)&b1[lane * 4];
    acc.x = fmaxf(acc.x + bb.x, 0.f);
    acc.y = fmaxf(acc.y + bb.y, 0.f);
    acc.z = fmaxf(acc.z + bb.z, 0.f);
    acc.w = fmaxf(acc.w + bb.w, 0.f);

    // h @ W2 (128x16) without touching global h
    float p[16];
    #pragma unroll
    for (int c = 0; c < 16; c++) {
        const float4 w = *(const float4*)&W2t[c * 128 + lane * 4];
        p[c] = acc.x * w.x + acc.y * w.y + acc.z * w.z + acc.w * w.w;
    }
    #pragma unroll
    for (int c = 0; c < 16; c++) {
        #pragma unroll
        for (int o = 16; o > 0; o >>= 1)
            p[c] += __shfl_down_sync(0xffffffffu, p[c], o);
    }
    if (lane == 0) {
        float al2 = 0.f, ar2 = 0.f;
        #pragma unroll
        for (int c = 0; c < 16; c++) {
            al2 = fmaf(p[c], asrc2[c], al2);
            ar2 = fmaf(p[c], adst2[c], ar2);
        }
        float4* o4 = (float4*)&g_xw2[d * 16];
        o4[0] = make_float4(p[0],  p[1],  p[2],  p[3]);
        o4[1] = make_float4(p[4],  p[5],  p[6],  p[7]);
        o4[2] = make_float4(p[8],  p[9],  p[10], p[11]);
        o4[3] = make_float4(p[12], p[13], p[14], p[15]);
        g_al2[d] = al2;
        g_ar2[d] = ar2;
    }
}

// ---------------- fused layer-2 aggregation + bias (proven) -----------------
#define F2_WARPS 8
__global__ void fused2_kernel(const float* __restrict__ b2,
                              float* __restrict__ out) {
    int t = threadIdx.x;
    int warp = t >> 5, lane = t & 31;
    int d = blockIdx.x * F2_WARPS + warp;
    if (d >= N_NODES) return;

    int row = g_row[d];
    int deg = g_deg[d];
    float ard = g_ar2[d];

    float den = 0.f;
    for (int i = lane; i < deg; i += 32) {
        int s = g_csr_src[row + i];
        den += __expf(lrelu(g_al2[s] + ard));
    }
    #pragma unroll
    for (int o = 16; o > 0; o >>= 1)
        den += __shfl_xor_sync(0xffffffffu, den, o);
    float inv = 1.f / den;

    int half = lane >> 4, l16 = lane & 15;
    float acc = 0.f;
    for (int i = half; i < deg; i += 2) {
        int s = g_csr_src[row + i];           // uniform per half-warp
        float alpha = __expf(lrelu(g_al2[s] + ard)) * inv;
        acc = fmaf(g_xw2[s * 16 + l16], alpha, acc);
    }
    acc += __shfl_xor_sync(0xffffffffu, acc, 16);
    if (lane < 16) out[d * 16 + lane] = acc + b2[lane];
}

// ---------------- launch ----------------------------------------------------
extern "C" void kernel_launch(void* const* d_in, const int* in_sizes, int n_in,
                              void* d_out, int out_size) {
    const float* x     = (const float*)d_in[0];
    const int*   ei    = (const int*)d_in[1];      // int32 (JAX x64 disabled)
    const float* W1    = (const float*)d_in[2];
    const float* asrc1 = (const float*)d_in[3];
    const float* adst1 = (const float*)d_in[4];
    const float* b1    = (const float*)d_in[5];
    const float* W2    = (const float*)d_in[6];
    const float* asrc2 = (const float*)d_in[7];
    const float* adst2 = (const float*)d_in[8];
    const float* b2    = (const float*)d_in[9];
    float* out = (float*)d_out;

    static void *p_deg = nullptr, *p_cursor = nullptr;
    if (!p_deg) {
        cudaGetSymbolAddress(&p_deg,    g_deg);
        cudaGetSymbolAddress(&p_cursor, g_cursor);
    }

    const int TB = 256;

    // CSR build
    cudaMemsetAsync(p_deg, 0, N_NODES * sizeof(int));
    cudaMemsetAsync(p_cursor, 0, sizeof(int));
    hist_kernel<<<2048, TB>>>(ei);
    scan_kernel<<<(N_NODES + SCAN_B - 1) / SCAN_B, SCAN_B>>>();
    scatter_kernel<<<2048, TB>>>(ei);

    // layer 1 GEMM (packed f32x2) + fused attention dots
    gemm1_kernel<<<(N_NODES + 127) / 128, 256>>>(x, W1, asrc1, adst1);

    // fused layer-1 aggregation + layer-2 projection
    fused1_kernel<<<(N_NODES + F1_WARPS - 1) / F1_WARPS, F1_WARPS * 32>>>(b1, W2, asrc2, adst2);

    // fused layer-2 aggregation + bias
    fused2_kernel<<<(N_NODES + F2_WARPS - 1) / F2_WARPS, F2_WARPS * 32>>>(b2, out);
}

// round 16
// speedup vs baseline: 1.0441x; 1.0441x over previous
#include <cuda_runtime.h>
#include <cuda_bf16.h>
#include <math.h>

#define N_NODES 100000
#define N_EDGES 1600000
#define E_TOT   (N_EDGES + N_NODES)
#define NEG_SLOPE 0.2f

// ---------------- scratch (static device globals) ---------------------------
__device__ __align__(16) float g_xw1[N_NODES * 128];
__device__ __align__(16) float g_al1[N_NODES * 4];
__device__ __align__(16) float g_ar1[N_NODES * 4];
__device__ __align__(16) float g_xw2[N_NODES * 16];
__device__ __align__(16) float g_al2[N_NODES];
__device__ __align__(16) float g_ar2[N_NODES];
__device__ int g_deg[N_NODES];     // in-degree (incl. self loop)
__device__ int g_row[N_NODES];     // CSR row start
__device__ int g_fill[N_NODES];    // scatter cursor
__device__ int g_csr_src[E_TOT];   // src node id per CSR slot
__device__ int g_cursor;           // global allocation cursor for scan

// ---------------- helpers ---------------------------------------------------
__device__ __forceinline__ float lrelu(float v) {
    return v > 0.f ? v : NEG_SLOPE * v;
}
// packed f32x2 ops (B300: FFMA2 = full-rate fp32; scalar FFMA is half-rate)
__device__ __forceinline__ unsigned long long pack2(float lo, float hi) {
    unsigned long long r;
    asm("mov.b64 %0, {%1, %2};" : "=l"(r) : "f"(lo), "f"(hi));
    return r;
}
__device__ __forceinline__ unsigned long long fma2(unsigned long long a,
                                                   unsigned long long b,
                                                   unsigned long long c) {
    unsigned long long d;
    asm("fma.rn.f32x2 %0, %1, %2, %3;" : "=l"(d) : "l"(a), "l"(b), "l"(c));
    return d;
}

// ---------------- CSR build --------------------------------------------------
__global__ void hist_kernel(const int* __restrict__ ei) {
    for (int i = blockIdx.x * blockDim.x + threadIdx.x; i < E_TOT; i += gridDim.x * blockDim.x) {
        int d = (i < N_EDGES) ? ei[N_EDGES + i] : (i - N_EDGES);
        atomicAdd(&g_deg[d], 1);
    }
}

#define SCAN_B 256
__global__ void scan_kernel() {
    __shared__ int sdata[SCAN_B];
    __shared__ int base;
    int t = threadIdx.x;
    int d = blockIdx.x * SCAN_B + t;
    int deg = (d < N_NODES) ? g_deg[d] : 0;
    sdata[t] = deg;
    __syncthreads();
    #pragma unroll
    for (int off = 1; off < SCAN_B; off <<= 1) {
        int v = 0;
        if (t >= off) v = sdata[t - off];
        __syncthreads();
        if (t >= off) sdata[t] += v;
        __syncthreads();
    }
    int incl = sdata[t];
    int excl = incl - deg;
    if (t == SCAN_B - 1) base = atomicAdd(&g_cursor, incl);
    __syncthreads();
    if (d < N_NODES) {
        int r = base + excl;
        g_row[d]  = r;
        g_fill[d] = r;
    }
}

__global__ void scatter_kernel(const int* __restrict__ ei) {
    for (int i = blockIdx.x * blockDim.x + threadIdx.x; i < E_TOT; i += gridDim.x * blockDim.x) {
        int s, d;
        if (i < N_EDGES) { s = ei[i]; d = ei[N_EDGES + i]; }
        else             { s = d = i - N_EDGES; }
        int pos = atomicAdd(&g_fill[d], 1);
        g_csr_src[pos] = s;
    }
}

// ---------------- layer 1 GEMM: x @ W1 (packed f32x2 SGEMM) -----------------
// 128x128 output tile per block, 256 threads (16x16), TM=8 x TN=8 per thread,
// BK=16. Accumulators held as 32 packed f32x2; inner product via fma.rn.f32x2.
// Epilogue computes per-head attention dots in-register (proven -8us vs split).
#define BK1 16
#define XS_PITCH 132                 // pad to kill staging STS conflicts
__global__ void __launch_bounds__(256)
gemm1_kernel(const float* __restrict__ x,
             const float* __restrict__ W1,
             const float* __restrict__ asrc,
             const float* __restrict__ adst) {
    __shared__ __align__(16) float xs[BK1 * XS_PITCH];  // xs[k][n] transposed
    __shared__ __align__(16) float ws[BK1 * 128];       // ws[k][c]
    int t  = threadIdx.x;
    int tx = t & 15;                 // col group
    int ty = t >> 4;                 // row group
    int nbase = blockIdx.x * 128;

    unsigned long long acc[8][4];
    #pragma unroll
    for (int r = 0; r < 8; r++)
        #pragma unroll
        for (int p = 0; p < 4; p++) acc[r][p] = 0ull;

    const float4* W4 = (const float4*)W1;
    float4* ws4s = (float4*)ws;

    for (int k0 = 0; k0 < 128; k0 += BK1) {
        // stage W1 rows [k0, k0+16): 512 float4, coalesced
        #pragma unroll
        for (int i = 0; i < 2; i++)
            ws4s[t + i * 256] = W4[k0 * 32 + t + i * 256];
        // stage x tile transposed: node n (128), k chunk j (4 float4s)
        #pragma unroll
        for (int i = 0; i < 2; i++) {
            int idx = t + i * 256;
            int n = idx >> 2, j = idx & 3;
            int node = nbase + n;
            float4 v = make_float4(0.f, 0.f, 0.f, 0.f);
            if (node < N_NODES)
                v = *(const float4*)&x[(size_t)node * 128 + k0 + j * 4];
            xs[(j * 4 + 0) * XS_PITCH + n] = v.x;
            xs[(j * 4 + 1) * XS_PITCH + n] = v.y;
            xs[(j * 4 + 2) * XS_PITCH + n] = v.z;
            xs[(j * 4 + 3) * XS_PITCH + n] = v.w;
        }
        __syncthreads();

        #pragma unroll
        for (int k = 0; k < BK1; k++) {
            float4 xa = *(const float4*)&xs[k * XS_PITCH + ty * 4];
            float4 xb = *(const float4*)&xs[k * XS_PITCH + ty * 4 + 64];
            float4 wa = *(const float4*)&ws[k * 128 + tx * 4];
            float4 wb = *(const float4*)&ws[k * 128 + tx * 4 + 64];
            unsigned long long wp0 = pack2(wa.x, wa.y);
            unsigned long long wp1 = pack2(wa.z, wa.w);
            unsigned long long wp2 = pack2(wb.x, wb.y);
            unsigned long long wp3 = pack2(wb.z, wb.w);
            float xr[8] = {xa.x, xa.y, xa.z, xa.w, xb.x, xb.y, xb.z, xb.w};
            #pragma unroll
            for (int r = 0; r < 8; r++) {
                unsigned long long xx = pack2(xr[r], xr[r]);
                acc[r][0] = fma2(xx, wp0, acc[r][0]);
                acc[r][1] = fma2(xx, wp1, acc[r][1]);
                acc[r][2] = fma2(xx, wp2, acc[r][2]);
                acc[r][3] = fma2(xx, wp3, acc[r][3]);
            }
        }
        __syncthreads();
    }

    // epilogue: write rows + in-register attention dots.
    float4 as_lo = ((const float4*)asrc)[tx];
    float4 as_hi = ((const float4*)asrc)[16 + tx];
    float4 ad_lo = ((const float4*)adst)[tx];
    float4 ad_hi = ((const float4*)adst)[16 + tx];
    int head_lo = tx >> 3;
    #pragma unroll
    for (int r = 0; r < 8; r++) {
        int rg = (r < 4) ? (ty * 4 + r) : (64 + ty * 4 + (r - 4));
        int node = nbase + rg;
        float2 f0 = *(float2*)&acc[r][0];
        float2 f1 = *(float2*)&acc[r][1];
        float2 f2 = *(float2*)&acc[r][2];
        float2 f3 = *(float2*)&acc[r][3];
        if (node < N_NODES) {
            *(float4*)&g_xw1[(size_t)node * 128 + tx * 4] =
                make_float4(f0.x, f0.y, f1.x, f1.y);
            *(float4*)&g_xw1[(size_t)node * 128 + 64 + tx * 4] =
                make_float4(f2.x, f2.y, f3.x, f3.y);
        }
        float al_lo = f0.x * as_lo.x + f0.y * as_lo.y + f1.x * as_lo.z + f1.y * as_lo.w;
        float al_hi = f2.x * as_hi.x + f2.y * as_hi.y + f3.x * as_hi.z + f3.y * as_hi.w;
        float ar_lo = f0.x * ad_lo.x + f0.y * ad_lo.y + f1.x * ad_lo.z + f1.y * ad_lo.w;
        float ar_hi = f2.x * ad_hi.x + f2.y * ad_hi.y + f3.x * ad_hi.z + f3.y * ad_hi.w;
        #pragma unroll
        for (int o = 4; o > 0; o >>= 1) {     // reduce within 8-lane head group
            al_lo += __shfl_xor_sync(0xffffffffu, al_lo, o);
            al_hi += __shfl_xor_sync(0xffffffffu, al_hi, o);
            ar_lo += __shfl_xor_sync(0xffffffffu, ar_lo, o);
            ar_hi += __shfl_xor_sync(0xffffffffu, ar_hi, o);
        }
        if ((tx & 7) == 0 && node < N_NODES) {
            g_al1[node * 4 + head_lo]     = al_lo;
            g_al1[node * 4 + 2 + head_lo] = al_hi;
            g_ar1[node * 4 + head_lo]     = ar_lo;
            g_ar1[node * 4 + 2 + head_lo] = ar_hi;
        }
    }
}

// ---------------- fused layer-1 aggregation + layer-2 GEMM ------------------
// One warp per dst node; zero atomics. SINGLE pass: unnormalized weighted sum
// + denominator accumulated together (every lane sees every edge, so each
// lane's den for its head is complete -- no reduction, no pass 1).
#define F1_WARPS 8
__global__ void fused1_kernel(const float* __restrict__ b1,
                              const float* __restrict__ W2,
                              const float* __restrict__ asrc2,
                              const float* __restrict__ adst2) {
    __shared__ __align__(16) float W2t[16 * 128];   // transposed: [c][k]
    int t = threadIdx.x;
    #pragma unroll
    for (int i = t; i < 16 * 128; i += F1_WARPS * 32) {
        int c = i >> 7, k = i & 127;
        W2t[i] = W2[k * 16 + c];
    }
    __syncthreads();

    int warp = t >> 5, lane = t & 31;
    int d = blockIdx.x * F1_WARPS + warp;
    if (d >= N_NODES) return;

    int row = g_row[d];
    int deg = g_deg[d];
    int head = lane >> 3;
    float ar_h = g_ar1[d * 4 + head];

    // single pass: acc_unnorm += w * v ; den += w
    float4 acc = make_float4(0.f, 0.f, 0.f, 0.f);
    float den = 0.f;
    for (int i = 0; i < deg; i++) {
        int s = g_csr_src[row + i];           // uniform across warp
        float a = g_al1[s * 4 + head];
        float w = __expf(lrelu(a + ar_h));
        den += w;
        float4 v = *(const float4*)&g_xw1[(size_t)s * 128 + lane * 4];
        acc.x = fmaf(v.x, w, acc.x);
        acc.y = fmaf(v.y, w, acc.y);
        acc.z = fmaf(v.z, w, acc.z);
        acc.w = fmaf(v.w, w, acc.w);
    }
    float inv = 1.f / den;

    // epilogue: normalize + bias + ReLU -> h row (registers)
    float4 bb = *(const float4*)&b1[lane * 4];
    acc.x = fmaxf(fmaf(acc.x, inv, bb.x), 0.f);
    acc.y = fmaxf(fmaf(acc.y, inv, bb.y), 0.f);
    acc.z = fmaxf(fmaf(acc.z, inv, bb.z), 0.f);
    acc.w = fmaxf(fmaf(acc.w, inv, bb.w), 0.f);

    // h @ W2 (128x16) without touching global h
    float p[16];
    #pragma unroll
    for (int c = 0; c < 16; c++) {
        const float4 w = *(const float4*)&W2t[c * 128 + lane * 4];
        p[c] = acc.x * w.x + acc.y * w.y + acc.z * w.z + acc.w * w.w;
    }
    #pragma unroll
    for (int c = 0; c < 16; c++) {
        #pragma unroll
        for (int o = 16; o > 0; o >>= 1)
            p[c] += __shfl_down_sync(0xffffffffu, p[c], o);
    }
    if (lane == 0) {
        float al2 = 0.f, ar2 = 0.f;
        #pragma unroll
        for (int c = 0; c < 16; c++) {
            al2 = fmaf(p[c], asrc2[c], al2);
            ar2 = fmaf(p[c], adst2[c], ar2);
        }
        float4* o4 = (float4*)&g_xw2[d * 16];
        o4[0] = make_float4(p[0],  p[1],  p[2],  p[3]);
        o4[1] = make_float4(p[4],  p[5],  p[6],  p[7]);
        o4[2] = make_float4(p[8],  p[9],  p[10], p[11]);
        o4[3] = make_float4(p[12], p[13], p[14], p[15]);
        g_al2[d] = al2;
        g_ar2[d] = ar2;
    }
}

// ---------------- fused layer-2 aggregation + bias --------------------------
// One warp per node; half-warps split edges. Single pass: unnormalized sum +
// den per half, both closed by one shfl_xor(16).
#define F2_WARPS 8
__global__ void fused2_kernel(const float* __restrict__ b2,
                              float* __restrict__ out) {
    int t = threadIdx.x;
    int warp = t >> 5, lane = t & 31;
    int d = blockIdx.x * F2_WARPS + warp;
    if (d >= N_NODES) return;

    int row = g_row[d];
    int deg = g_deg[d];
    float ard = g_ar2[d];

    int half = lane >> 4, l16 = lane & 15;
    float acc = 0.f, den = 0.f;
    for (int i = half; i < deg; i += 2) {
        int s = g_csr_src[row + i];           // uniform per half-warp
        float w = __expf(lrelu(g_al2[s] + ard));
        den += w;
        acc = fmaf(g_xw2[s * 16 + l16], w, acc);
    }
    acc += __shfl_xor_sync(0xffffffffu, acc, 16);
    den += __shfl_xor_sync(0xffffffffu, den, 16);
    if (lane < 16) out[d * 16 + lane] = acc / den + b2[lane];
}

// ---------------- launch ----------------------------------------------------
extern "C" void kernel_launch(void* const* d_in, const int* in_sizes, int n_in,
                              void* d_out, int out_size) {
    const float* x     = (const float*)d_in[0];
    const int*   ei    = (const int*)d_in[1];      // int32 (JAX x64 disabled)
    const float* W1    = (const float*)d_in[2];
    const float* asrc1 = (const float*)d_in[3];
    const float* adst1 = (const float*)d_in[4];
    const float* b1    = (const float*)d_in[5];
    const float* W2    = (const float*)d_in[6];
    const float* asrc2 = (const float*)d_in[7];
    const float* adst2 = (const float*)d_in[8];
    const float* b2    = (const float*)d_in[9];
    float* out = (float*)d_out;

    static void *p_deg = nullptr, *p_cursor = nullptr;
    if (!p_deg) {
        cudaGetSymbolAddress(&p_deg,    g_deg);
        cudaGetSymbolAddress(&p_cursor, g_cursor);
    }

    const int TB = 256;

    // CSR build
    cudaMemsetAsync(p_deg, 0, N_NODES * sizeof(int));
    cudaMemsetAsync(p_cursor, 0, sizeof(int));
    hist_kernel<<<2048, TB>>>(ei);
    scan_kernel<<<(N_NODES + SCAN_B - 1) / SCAN_B, SCAN_B>>>();
    scatter_kernel<<<2048, TB>>>(ei);

    // layer 1 GEMM (packed f32x2) + fused attention dots
    gemm1_kernel<<<(N_NODES + 127) / 128, 256>>>(x, W1, asrc1, adst1);

    // fused layer-1 aggregation + layer-2 projection (single-pass softmax)
    fused1_kernel<<<(N_NODES + F1_WARPS - 1) / F1_WARPS, F1_WARPS * 32>>>(b1, W2, asrc2, adst2);

    // fused layer-2 aggregation + bias (single-pass softmax)
    fused2_kernel<<<(N_NODES + F2_WARPS - 1) / F2_WARPS, F2_WARPS * 32>>>(b2, out);
}